// round 4
// baseline (speedup 1.0000x reference)
#include <cuda_runtime.h>

#define N_CELLS 776
#define N_ANCHORS 3
#define N_CH 7
#define CONF_THRESH 0.8f
#define NO_OBJECT 0.5f

__global__ __launch_bounds__(1024, 1)
void yolo_loss_kernel(const float* __restrict__ pred,
                      const float* __restrict__ label,
                      float* __restrict__ out) {
    const int tid = threadIdx.x;

    // Broadcast label (7 floats) — L1-resident after first access.
    const float lx = __ldg(&label[0]);
    const float ly = __ldg(&label[1]);
    const float lw = __ldg(&label[2]);
    const float lh = __ldg(&label[3]);
    const float lc = __ldg(&label[4]);
    const float l5 = __ldg(&label[5]);
    const float l6 = __ldg(&label[6]);

    float local = 0.0f;

    if (tid < N_CELLS) {
        const float* p = pred + tid * (N_ANCHORS * N_CH);

        // Load all 21 floats for this cell.
        float v[N_ANCHORS * N_CH];
        #pragma unroll
        for (int i = 0; i < N_ANCHORS * N_CH; i++) v[i] = p[i];

        // argmax over anchor IoUs (strict > keeps first max, matching jnp.argmax)
        float best_iou = -1.0f;
        int best = 0;
        #pragma unroll
        for (int a = 0; a < N_ANCHORS; a++) {
            const float px = v[a * N_CH + 0];
            const float py = v[a * N_CH + 1];
            const float pw = v[a * N_CH + 2];
            const float ph = v[a * N_CH + 3];
            const float ax = fmaxf(px - pw * 0.5f, lx - lw * 0.5f);
            const float ay = fmaxf(py - ph * 0.5f, ly - lh * 0.5f);
            const float bx = fminf(px + pw * 0.5f, lx + lw * 0.5f);
            const float by = fminf(py + ph * 0.5f, ly + lh * 0.5f);
            const float inter = fabsf(fmaxf(bx - ax, 0.0f) * fmaxf(by - ay, 0.0f));
            const float area_a = fabsf(pw * ph);
            const float area_b = fabsf(lw * lh);
            const float iou = inter / (area_a + area_b - inter);
            if (iou > best_iou) { best_iou = iou; best = a; }
        }

        const float b0 = v[best * N_CH + 0];
        const float b1 = v[best * N_CH + 1];
        const float b4 = v[best * N_CH + 4];
        const float b5 = v[best * N_CH + 5];
        const float b6 = v[best * N_CH + 6];

        const float dx = lx - b0;
        const float dy = ly - b1;
        const float xy_loss = dx * dx + dy * dy;

        // NOTE: reference uses label[0]/label[1] and best[:,0]/best[:,1] (x,y)
        // inside the sqrt terms — replicate verbatim.
        const float swx = sqrtf(lx) - sqrtf(b0);
        const float swy = sqrtf(ly) - sqrtf(b1);
        const float wh_loss = swx * swx + swy * swy;

        const float coord_loss = xy_loss + wh_loss;

        const bool has_obj = b4 > CONF_THRESH;
        float class_loss = 0.0f;
        if (has_obj) {
            const float d5 = l5 - b5;
            const float d6 = l6 - b6;
            class_loss = d5 * d5 + d6 * d6;
        }
        const float dc = lc - b4;
        const float conf_sq = dc * dc;
        const float conf_loss = has_obj ? conf_sq : NO_OBJECT * conf_sq;

        local = coord_loss + class_loss + conf_loss;
    }

    // Block reduction: warp shuffle then smem across 32 warps.
    #pragma unroll
    for (int off = 16; off > 0; off >>= 1)
        local += __shfl_down_sync(0xFFFFFFFFu, local, off);

    __shared__ float warp_sums[32];
    const int lane = tid & 31;
    const int wid = tid >> 5;
    if (lane == 0) warp_sums[wid] = local;
    __syncthreads();

    if (wid == 0) {
        float s = warp_sums[lane];
        #pragma unroll
        for (int off = 16; off > 0; off >>= 1)
            s += __shfl_down_sync(0xFFFFFFFFu, s, off);
        if (lane == 0) out[0] = s;
    }
}

extern "C" void kernel_launch(void* const* d_in, const int* in_sizes, int n_in,
                              void* d_out, int out_size) {
    const float* pred  = (const float*)d_in[0];
    const float* label = (const float*)d_in[1];
    float* out = (float*)d_out;
    yolo_loss_kernel<<<1, 1024>>>(pred, label, out);
}